// round 1
// baseline (speedup 1.0000x reference)
#include <cuda_runtime.h>
#include <math.h>

#define Bn 256
#define Vn 6890
#define NJn 24
#define NBn 10
#define NPn 207
#define NJRn 43
#define Cn (Vn*3)      /* 20670 */
#define KC (NBn+NPn)   /* 217 */

// ---------------- scratch (static device allocations; no runtime alloc) ----
__device__ float g_coef[Bn*KC];            // [b][217]: beta(10) ++ pose_feature(207)
__device__ float g_A[Bn*NJn*12];           // [b][24][3][4]
__device__ float g_JrSD[NJn*NBn*3];        // [j][k][d]
__device__ float g_JrVT[NJn*3];            // [j][d]
__device__ float g_vposed[(size_t)Bn*Cn];  // 21.2 MB
__device__ float g_jpart[16*(size_t)Bn*NJRn*3]; // per-vsplit joint partials

__constant__ int PARc[NJn] = {0,0,0,0,1,2,3,4,5,6,7,8,9,9,9,12,13,14,16,17,18,19,20,21};

// ---------------- K0: precompute Jr*vt and Jr*sd factors ------------------
__global__ void k_pre(const float* __restrict__ Jr, const float* __restrict__ vt,
                      const float* __restrict__ sd) {
    int j = blockIdx.x;
    float aVT[3] = {0.f, 0.f, 0.f};
    float aSD[NBn][3];
#pragma unroll
    for (int k = 0; k < NBn; k++)
#pragma unroll
        for (int d = 0; d < 3; d++) aSD[k][d] = 0.f;

    for (int v = threadIdx.x; v < Vn; v += blockDim.x) {
        float jr = Jr[j*Vn + v];
#pragma unroll
        for (int d = 0; d < 3; d++) aVT[d] += jr * vt[v*3 + d];
#pragma unroll
        for (int k = 0; k < NBn; k++)
#pragma unroll
            for (int d = 0; d < 3; d++)
                aSD[k][d] += jr * sd[(size_t)k*Cn + v*3 + d];
    }
    // warp shuffle reduce 33 values
#pragma unroll
    for (int off = 16; off; off >>= 1) {
#pragma unroll
        for (int d = 0; d < 3; d++) aVT[d] += __shfl_down_sync(0xffffffffu, aVT[d], off);
#pragma unroll
        for (int k = 0; k < NBn; k++)
#pragma unroll
            for (int d = 0; d < 3; d++) aSD[k][d] += __shfl_down_sync(0xffffffffu, aSD[k][d], off);
    }
    __shared__ float red[8][33];
    int w = threadIdx.x >> 5, l = threadIdx.x & 31;
    if (l == 0) {
#pragma unroll
        for (int d = 0; d < 3; d++) red[w][d] = aVT[d];
#pragma unroll
        for (int k = 0; k < NBn; k++)
#pragma unroll
            for (int d = 0; d < 3; d++) red[w][3 + k*3 + d] = aSD[k][d];
    }
    __syncthreads();
    if (threadIdx.x < 33) {
        float s = 0.f;
#pragma unroll
        for (int ww = 0; ww < 8; ww++) s += red[ww][threadIdx.x];
        if (threadIdx.x < 3) g_JrVT[j*3 + threadIdx.x] = s;
        else                 g_JrSD[j*30 + (threadIdx.x - 3)] = s;
    }
}

// ---------------- K1: per-batch rodrigues + J + kinematic chain + A + coef -
__global__ void k_batch(const float* __restrict__ beta, const float* __restrict__ theta) {
    int b = blockIdx.x;
    int lane = threadIdx.x;
    __shared__ float Rs[NJn*9];
    __shared__ float Jsh[NJn*3];
    __shared__ float G[NJn*12];

    if (lane < NJn) {
        int i = lane;
        float t0 = theta[b*72 + i*3 + 0];
        float t1 = theta[b*72 + i*3 + 1];
        float t2 = theta[b*72 + i*3 + 2];
        float a0 = t0 + 1e-8f, a1 = t1 + 1e-8f, a2 = t2 + 1e-8f;
        float angle = sqrtf(a0*a0 + a1*a1 + a2*a2);
        float inv = 1.0f / angle;
        float r0 = t0*inv, r1 = t1*inv, r2 = t2*inv;
        float s, c;
        sincosf(0.5f*angle, &s, &c);
        float qw = c, qx = s*r0, qy = s*r1, qz = s*r2;
        float qn = rsqrtf(qw*qw + qx*qx + qy*qy + qz*qz);
        qw *= qn; qx *= qn; qy *= qn; qz *= qn;
        float xx = qx*qx, yy = qy*qy, zz = qz*qz;
        float xy = qx*qy, xz = qx*qz, yz = qy*qz;
        float wx = qw*qx, wy = qw*qy, wz = qw*qz;
        Rs[i*9+0] = 1.f - 2.f*(yy+zz); Rs[i*9+1] = 2.f*(xy-wz);       Rs[i*9+2] = 2.f*(xz+wy);
        Rs[i*9+3] = 2.f*(xy+wz);       Rs[i*9+4] = 1.f - 2.f*(xx+zz); Rs[i*9+5] = 2.f*(yz-wx);
        Rs[i*9+6] = 2.f*(xz-wy);       Rs[i*9+7] = 2.f*(yz+wx);       Rs[i*9+8] = 1.f - 2.f*(xx+yy);
        // J[b][i] via factorization
#pragma unroll
        for (int d = 0; d < 3; d++) {
            float sj = g_JrVT[i*3 + d];
#pragma unroll
            for (int k = 0; k < NBn; k++)
                sj += beta[b*NBn + k] * g_JrSD[i*30 + k*3 + d];
            Jsh[i*3 + d] = sj;
        }
    }
    __syncwarp();
    // root: G0 = [Rs0 @ diag(1,-1,-1) | J0]
    if (lane < 12) {
        int r = lane >> 2, c = lane & 3;
        float v;
        if (c < 3) v = Rs[r*3 + c] * (c == 0 ? 1.f : -1.f);
        else       v = Jsh[r];
        G[lane] = v;
    }
    __syncwarp();
    for (int i = 1; i < NJn; i++) {
        int p = PARc[i];
        float val = 0.f;
        if (lane < 12) {
            int r = lane >> 2, c = lane & 3;
#pragma unroll
            for (int m = 0; m < 3; m++) {
                float L = (c < 3) ? Rs[i*9 + m*3 + c] : (Jsh[i*3 + m] - Jsh[p*3 + m]);
                val += G[p*12 + r*4 + m] * L;
            }
            if (c == 3) val += G[p*12 + r*4 + 3];
        }
        __syncwarp();
        if (lane < 12) G[i*12 + lane] = val;
        __syncwarp();
    }
    // A = G with translation t' = G_t - G_R @ J
    if (lane < NJn) {
        int i = lane;
        float j0 = Jsh[i*3+0], j1 = Jsh[i*3+1], j2 = Jsh[i*3+2];
#pragma unroll
        for (int r = 0; r < 3; r++) {
            float g0 = G[i*12 + r*4 + 0], g1 = G[i*12 + r*4 + 1];
            float g2 = G[i*12 + r*4 + 2], g3 = G[i*12 + r*4 + 3];
            float* A = &g_A[((size_t)b*NJn + i)*12 + r*4];
            A[0] = g0; A[1] = g1; A[2] = g2;
            A[3] = g3 - (g0*j0 + g1*j1 + g2*j2);
        }
    }
    // coef = [beta(10), pose_feature(207)]
    for (int idx = lane; idx < KC; idx += 32) {
        float v;
        if (idx < NBn) v = beta[b*NBn + idx];
        else {
            int e = idx - NBn;
            int i = e / 9 + 1;
            int rr = e % 9;
            v = Rs[i*9 + rr] - ((rr == 0 || rr == 4 || rr == 8) ? 1.f : 0.f);
        }
        g_coef[b*KC + idx] = v;
    }
}

// ---------------- K2: v_posed GEMM (M=256,N=20670,K=217), 32 batches/block -
__global__ void k_vposed(const float* __restrict__ vt, const float* __restrict__ sd,
                         const float* __restrict__ pd) {
    __shared__ float sh[KC*32];           // [k][bb]
    int b0 = blockIdx.y * 32;
    for (int idx = threadIdx.x; idx < KC*32; idx += blockDim.x) {
        int bb = idx / KC, k = idx - bb*KC;
        sh[k*32 + bb] = g_coef[(b0 + bb)*KC + k];
    }
    __syncthreads();
    int c = blockIdx.x * blockDim.x + threadIdx.x;
    if (c >= Cn) return;

    float acc[32];
    float vtc = vt[c];
#pragma unroll
    for (int i = 0; i < 32; i++) acc[i] = vtc;

    const float4* sh4 = (const float4*)sh;
#pragma unroll 2
    for (int k = 0; k < NBn; k++) {
        float pv = sd[(size_t)k*Cn + c];
        const float4* cf = sh4 + k*8;
#pragma unroll
        for (int g = 0; g < 8; g++) {
            float4 q = cf[g];
            acc[4*g+0] += q.x*pv; acc[4*g+1] += q.y*pv;
            acc[4*g+2] += q.z*pv; acc[4*g+3] += q.w*pv;
        }
    }
#pragma unroll 2
    for (int k = 0; k < NPn; k++) {
        float pv = pd[(size_t)k*Cn + c];
        const float4* cf = sh4 + (NBn + k)*8;
#pragma unroll
        for (int g = 0; g < 8; g++) {
            float4 q = cf[g];
            acc[4*g+0] += q.x*pv; acc[4*g+1] += q.y*pv;
            acc[4*g+2] += q.z*pv; acc[4*g+3] += q.w*pv;
        }
    }
#pragma unroll
    for (int i = 0; i < 32; i++)
        g_vposed[(size_t)(b0 + i)*Cn + c] = acc[i];
}

// ---------------- K3: LBS skinning -> verts (weights broadcast: use slice 0)
__global__ void k_skin(const float* __restrict__ wts, float* __restrict__ out) {
    __shared__ float A_sh[8*NJn*12];      // 9216 B
    int b0 = blockIdx.y * 8;
    for (int idx = threadIdx.x; idx < 8*NJn*12; idx += blockDim.x)
        A_sh[idx] = g_A[(size_t)b0*NJn*12 + idx];
    __syncthreads();
    int v = blockIdx.x * blockDim.x + threadIdx.x;
    if (v >= Vn) return;

    float w[NJn];
    const float4* wp = (const float4*)(wts + (size_t)v*NJn); // 96B-aligned
#pragma unroll
    for (int q = 0; q < 6; q++) {
        float4 t = wp[q];
        w[4*q+0] = t.x; w[4*q+1] = t.y; w[4*q+2] = t.z; w[4*q+3] = t.w;
    }
#pragma unroll 1
    for (int bb = 0; bb < 8; bb++) {
        int b = b0 + bb;
        const float* vp = g_vposed + (size_t)b*Cn + 3*v;
        float px = vp[0], py = vp[1], pz = vp[2];
        float m00=0,m01=0,m02=0,m03=0, m10=0,m11=0,m12=0,m13=0, m20=0,m21=0,m22=0,m23=0;
        const float4* Ab = (const float4*)(A_sh + bb*NJn*12);
#pragma unroll
        for (int j = 0; j < NJn; j++) {
            float wj = w[j];
            float4 a0 = Ab[j*3+0], a1 = Ab[j*3+1], a2 = Ab[j*3+2];
            m00 += wj*a0.x; m01 += wj*a0.y; m02 += wj*a0.z; m03 += wj*a0.w;
            m10 += wj*a1.x; m11 += wj*a1.y; m12 += wj*a1.z; m13 += wj*a1.w;
            m20 += wj*a2.x; m21 += wj*a2.y; m22 += wj*a2.z; m23 += wj*a2.w;
        }
        float* o = out + (size_t)b*Cn + 3*v;
        o[0] = m00*px + m01*py + m02*pz + m03;
        o[1] = m10*px + m11*py + m12*pz + m13;
        o[2] = m20*px + m21*py + m22*pz + m23;
    }
}

// ---------------- K4: joints partials (deterministic, no atomics) ----------
__global__ void k_joints(const float* __restrict__ jr2, const float* __restrict__ out) {
    __shared__ float4 vsh[16*64];         // [bb][vv], .w unused
    __shared__ float  jsh[43*65];         // padded rows
    const float* verts = out;
    int b0 = blockIdx.y * 16;
    int vs = blockIdx.x;
    int vstart = vs * 431;
    int vend = min(vstart + 431, Vn);

    float ax[3] = {0,0,0}, ay[3] = {0,0,0}, az[3] = {0,0,0};
    for (int vbase = vstart; vbase < vend; vbase += 64) {
        int vcnt = min(64, vend - vbase);
        for (int idx = threadIdx.x; idx < 16*64*3; idx += 256) {
            int bb = idx / 192; int rem = idx - bb*192;
            int vv = rem / 3;   int d = rem - vv*3;
            float val = (vv < vcnt) ? verts[(size_t)(b0 + bb)*Cn + (size_t)(vbase + vv)*3 + d] : 0.f;
            ((float*)&vsh[bb*64 + vv])[d] = val;
        }
        for (int idx = threadIdx.x; idx < 43*64; idx += 256) {
            int j = idx >> 6; int vv = idx & 63;
            jsh[j*65 + vv] = (vv < vcnt) ? jr2[(size_t)j*Vn + vbase + vv] : 0.f;
        }
        __syncthreads();
#pragma unroll
        for (int t = 0; t < 3; t++) {
            int pid = threadIdx.x + t*256;
            if (pid < 688) {
                int bb = pid / 43, j = pid - bb*43;
                const float4* vp = &vsh[bb*64];
                const float*  jp = &jsh[j*65];
                float sx = 0, sy = 0, sz = 0;
#pragma unroll 4
                for (int vv = 0; vv < 64; vv++) {
                    float jr = jp[vv]; float4 p = vp[vv];
                    sx += jr*p.x; sy += jr*p.y; sz += jr*p.z;
                }
                ax[t] += sx; ay[t] += sy; az[t] += sz;
            }
        }
        __syncthreads();
    }
#pragma unroll
    for (int t = 0; t < 3; t++) {
        int pid = threadIdx.x + t*256;
        if (pid < 688) {
            int bb = pid / 43, j = pid - bb*43;
            float* jo = &g_jpart[((size_t)vs*Bn*NJRn + (size_t)(b0 + bb)*NJRn + j)*3];
            jo[0] = ax[t]; jo[1] = ay[t]; jo[2] = az[t];
        }
    }
}

// ---------------- K5: reduce joint partials into output --------------------
__global__ void k_jred(float* __restrict__ out) {
    int i = blockIdx.x * blockDim.x + threadIdx.x;
    const int n = Bn*NJRn*3;
    if (i < n) {
        float s = 0.f;
#pragma unroll
        for (int vs = 0; vs < 16; vs++) s += g_jpart[(size_t)vs*n + i];
        out[(size_t)Bn*Cn + i] = s;
    }
}

// ---------------- launch ---------------------------------------------------
extern "C" void kernel_launch(void* const* d_in, const int* in_sizes, int n_in,
                              void* d_out, int out_size) {
    const float* beta  = (const float*)d_in[0];
    const float* theta = (const float*)d_in[1];
    const float* vt    = (const float*)d_in[2];
    const float* sd    = (const float*)d_in[3];
    const float* pd    = (const float*)d_in[4];
    const float* Jr    = (const float*)d_in[5];
    const float* jr2   = (const float*)d_in[6];
    const float* wts   = (const float*)d_in[7];
    float* out = (float*)d_out;

    k_pre<<<NJn, 256>>>(Jr, vt, sd);
    k_batch<<<Bn, 32>>>(beta, theta);
    k_vposed<<<dim3((Cn + 255)/256, Bn/32), 256>>>(vt, sd, pd);
    k_skin<<<dim3((Vn + 255)/256, Bn/8), 256>>>(wts, out);
    k_joints<<<dim3(16, 16), 256>>>(jr2, out);
    k_jred<<<(Bn*NJRn*3 + 255)/256, 256>>>(out);
}

// round 2
// speedup vs baseline: 1.0373x; 1.0373x over previous
#include <cuda_runtime.h>
#include <math.h>

#define Bn 256
#define Vn 6890
#define NJn 24
#define NBn 10
#define NPn 207
#define NJRn 43
#define Cn (Vn*3)      /* 20670 */
#define KC (NBn+NPn)   /* 217 */

typedef unsigned long long ull;

__device__ __forceinline__ ull pk(float lo, float hi) {
    ull r; asm("mov.b64 %0,{%1,%2};" : "=l"(r) : "f"(lo), "f"(hi)); return r;
}
__device__ __forceinline__ void upk(ull v, float& lo, float& hi) {
    asm("mov.b64 {%0,%1},%2;" : "=f"(lo), "=f"(hi) : "l"(v));
}
__device__ __forceinline__ ull fma2(ull a, ull b, ull c) {
    ull d; asm("fma.rn.f32x2 %0,%1,%2,%3;" : "=l"(d) : "l"(a), "l"(b), "l"(c)); return d;
}
__device__ __forceinline__ ull mul2(ull a, ull b) {
    ull d; asm("mul.rn.f32x2 %0,%1,%2;" : "=l"(d) : "l"(a), "l"(b)); return d;
}
__device__ __forceinline__ ull add2(ull a, ull b) {
    ull d; asm("add.rn.f32x2 %0,%1,%2;" : "=l"(d) : "l"(a), "l"(b)); return d;
}

// ---------------- scratch ---------------------------------------------------
__device__ float g_coef[Bn*KC];            // [b][217]
__device__ float g_A[Bn*NJn*12];           // [b][24][3][4]
__device__ float g_JrSD[NJn*NBn*3];
__device__ float g_JrVT[NJn*3];
__device__ float g_vposed[(size_t)Bn*Cn];  // 21.2 MB
__device__ float g_jpart[16*(size_t)Bn*NJRn*3];

__constant__ int PARc[NJn] = {0,0,0,0,1,2,3,4,5,6,7,8,9,9,9,12,13,14,16,17,18,19,20,21};

// ---------------- K0: Jr*vt and Jr*sd factors ------------------------------
__global__ void k_pre(const float* __restrict__ Jr, const float* __restrict__ vt,
                      const float* __restrict__ sd) {
    int j = blockIdx.x;
    float aVT[3] = {0.f, 0.f, 0.f};
    float aSD[NBn][3];
#pragma unroll
    for (int k = 0; k < NBn; k++)
#pragma unroll
        for (int d = 0; d < 3; d++) aSD[k][d] = 0.f;

    for (int v = threadIdx.x; v < Vn; v += blockDim.x) {
        float jr = Jr[j*Vn + v];
#pragma unroll
        for (int d = 0; d < 3; d++) aVT[d] += jr * vt[v*3 + d];
#pragma unroll
        for (int k = 0; k < NBn; k++)
#pragma unroll
            for (int d = 0; d < 3; d++)
                aSD[k][d] += jr * sd[(size_t)k*Cn + v*3 + d];
    }
#pragma unroll
    for (int off = 16; off; off >>= 1) {
#pragma unroll
        for (int d = 0; d < 3; d++) aVT[d] += __shfl_down_sync(0xffffffffu, aVT[d], off);
#pragma unroll
        for (int k = 0; k < NBn; k++)
#pragma unroll
            for (int d = 0; d < 3; d++) aSD[k][d] += __shfl_down_sync(0xffffffffu, aSD[k][d], off);
    }
    __shared__ float red[8][33];
    int w = threadIdx.x >> 5, l = threadIdx.x & 31;
    if (l == 0) {
#pragma unroll
        for (int d = 0; d < 3; d++) red[w][d] = aVT[d];
#pragma unroll
        for (int k = 0; k < NBn; k++)
#pragma unroll
            for (int d = 0; d < 3; d++) red[w][3 + k*3 + d] = aSD[k][d];
    }
    __syncthreads();
    if (threadIdx.x < 33) {
        float s = 0.f;
#pragma unroll
        for (int ww = 0; ww < 8; ww++) s += red[ww][threadIdx.x];
        if (threadIdx.x < 3) g_JrVT[j*3 + threadIdx.x] = s;
        else                 g_JrSD[j*30 + (threadIdx.x - 3)] = s;
    }
}

// ---------------- K1: rodrigues + chain + A + coef --------------------------
__global__ void k_batch(const float* __restrict__ beta, const float* __restrict__ theta) {
    int b = blockIdx.x;
    int lane = threadIdx.x;
    __shared__ float Rs[NJn*9];
    __shared__ float Jsh[NJn*3];
    __shared__ float G[NJn*12];

    if (lane < NJn) {
        int i = lane;
        float t0 = theta[b*72 + i*3 + 0];
        float t1 = theta[b*72 + i*3 + 1];
        float t2 = theta[b*72 + i*3 + 2];
        float a0 = t0 + 1e-8f, a1 = t1 + 1e-8f, a2 = t2 + 1e-8f;
        float angle = sqrtf(a0*a0 + a1*a1 + a2*a2);
        float inv = 1.0f / angle;
        float r0 = t0*inv, r1 = t1*inv, r2 = t2*inv;
        float s, c;
        sincosf(0.5f*angle, &s, &c);
        float qw = c, qx = s*r0, qy = s*r1, qz = s*r2;
        float qn = rsqrtf(qw*qw + qx*qx + qy*qy + qz*qz);
        qw *= qn; qx *= qn; qy *= qn; qz *= qn;
        float xx = qx*qx, yy = qy*qy, zz = qz*qz;
        float xy = qx*qy, xz = qx*qz, yz = qy*qz;
        float wx = qw*qx, wy = qw*qy, wz = qw*qz;
        Rs[i*9+0] = 1.f - 2.f*(yy+zz); Rs[i*9+1] = 2.f*(xy-wz);       Rs[i*9+2] = 2.f*(xz+wy);
        Rs[i*9+3] = 2.f*(xy+wz);       Rs[i*9+4] = 1.f - 2.f*(xx+zz); Rs[i*9+5] = 2.f*(yz-wx);
        Rs[i*9+6] = 2.f*(xz-wy);       Rs[i*9+7] = 2.f*(yz+wx);       Rs[i*9+8] = 1.f - 2.f*(xx+yy);
#pragma unroll
        for (int d = 0; d < 3; d++) {
            float sj = g_JrVT[i*3 + d];
#pragma unroll
            for (int k = 0; k < NBn; k++)
                sj += beta[b*NBn + k] * g_JrSD[i*30 + k*3 + d];
            Jsh[i*3 + d] = sj;
        }
    }
    __syncwarp();
    if (lane < 12) {
        int r = lane >> 2, c = lane & 3;
        float v;
        if (c < 3) v = Rs[r*3 + c] * (c == 0 ? 1.f : -1.f);
        else       v = Jsh[r];
        G[lane] = v;
    }
    __syncwarp();
    for (int i = 1; i < NJn; i++) {
        int p = PARc[i];
        float val = 0.f;
        if (lane < 12) {
            int r = lane >> 2, c = lane & 3;
#pragma unroll
            for (int m = 0; m < 3; m++) {
                float L = (c < 3) ? Rs[i*9 + m*3 + c] : (Jsh[i*3 + m] - Jsh[p*3 + m]);
                val += G[p*12 + r*4 + m] * L;
            }
            if (c == 3) val += G[p*12 + r*4 + 3];
        }
        __syncwarp();
        if (lane < 12) G[i*12 + lane] = val;
        __syncwarp();
    }
    if (lane < NJn) {
        int i = lane;
        float j0 = Jsh[i*3+0], j1 = Jsh[i*3+1], j2 = Jsh[i*3+2];
#pragma unroll
        for (int r = 0; r < 3; r++) {
            float g0 = G[i*12 + r*4 + 0], g1 = G[i*12 + r*4 + 1];
            float g2 = G[i*12 + r*4 + 2], g3 = G[i*12 + r*4 + 3];
            float* A = &g_A[((size_t)b*NJn + i)*12 + r*4];
            A[0] = g0; A[1] = g1; A[2] = g2;
            A[3] = g3 - (g0*j0 + g1*j1 + g2*j2);
        }
    }
    for (int idx = lane; idx < KC; idx += 32) {
        float v;
        if (idx < NBn) v = beta[b*NBn + idx];
        else {
            int e = idx - NBn;
            int i = e / 9 + 1;
            int rr = e % 9;
            v = Rs[i*9 + rr] - ((rr == 0 || rr == 4 || rr == 8) ? 1.f : 0.f);
        }
        g_coef[b*KC + idx] = v;
    }
}

// ---------------- K2: v_posed GEMM with packed f32x2 ------------------------
__global__ void k_vposed(const float* __restrict__ vt, const float* __restrict__ sd,
                         const float* __restrict__ pd) {
    __shared__ float sh[KC*32];           // [k][bb]
    int b0 = blockIdx.y * 32;
    for (int idx = threadIdx.x; idx < KC*32; idx += blockDim.x) {
        int bb = idx / KC, k = idx - bb*KC;
        sh[k*32 + bb] = g_coef[(b0 + bb)*KC + k];
    }
    __syncthreads();
    int c = blockIdx.x * blockDim.x + threadIdx.x;
    if (c >= Cn) return;

    ull acc[16];
    float vtc = vt[c];
    ull vt2 = pk(vtc, vtc);
#pragma unroll
    for (int i = 0; i < 16; i++) acc[i] = vt2;

    const ulonglong2* sh8 = (const ulonglong2*)sh;   // 8 ulonglong2 per k
    const float* sptr = sd + c;
    const float* pptr = pd + c;

    float pv_next = sptr[0];
#pragma unroll 2
    for (int k = 0; k < KC; k++) {
        float pv = pv_next;
        int kk = k + 1;
        if (kk < KC)
            pv_next = (kk < NBn) ? sptr[(size_t)kk*Cn] : pptr[(size_t)(kk - NBn)*Cn];
        ull pv2 = pk(pv, pv);
        const ulonglong2* cf = sh8 + k*8;
#pragma unroll
        for (int g = 0; g < 8; g++) {
            ulonglong2 q = cf[g];
            acc[2*g]   = fma2(q.x, pv2, acc[2*g]);
            acc[2*g+1] = fma2(q.y, pv2, acc[2*g+1]);
        }
    }
#pragma unroll
    for (int g = 0; g < 8; g++) {
        float a, b;
        upk(acc[2*g], a, b);
        g_vposed[(size_t)(b0 + 4*g + 0)*Cn + c] = a;
        g_vposed[(size_t)(b0 + 4*g + 1)*Cn + c] = b;
        upk(acc[2*g+1], a, b);
        g_vposed[(size_t)(b0 + 4*g + 2)*Cn + c] = a;
        g_vposed[(size_t)(b0 + 4*g + 3)*Cn + c] = b;
    }
}

// ---------------- K3: LBS skinning with packed f32x2 ------------------------
__global__ void k_skin(const float* __restrict__ wts, float* __restrict__ out) {
    __shared__ float A_sh[8*NJn*12];      // 9216 B
    int b0 = blockIdx.y * 8;
    for (int idx = threadIdx.x; idx < 8*NJn*12; idx += blockDim.x)
        A_sh[idx] = g_A[(size_t)b0*NJn*12 + idx];
    __syncthreads();
    int v = blockIdx.x * blockDim.x + threadIdx.x;
    if (v >= Vn) return;

    float w[NJn];
    const float4* wp = (const float4*)(wts + (size_t)v*NJn);
#pragma unroll
    for (int q = 0; q < 6; q++) {
        float4 t = wp[q];
        w[4*q+0] = t.x; w[4*q+1] = t.y; w[4*q+2] = t.z; w[4*q+3] = t.w;
    }
#pragma unroll 1
    for (int bb = 0; bb < 8; bb++) {
        int b = b0 + bb;
        const float* vp = g_vposed + (size_t)b*Cn + 3*v;
        float px = vp[0], py = vp[1], pz = vp[2];

        ull m01[3] = {0,0,0}, m23[3] = {0,0,0};
        const ulonglong2* Ab = (const ulonglong2*)(A_sh + bb*NJn*12);
#pragma unroll
        for (int j = 0; j < NJn; j++) {
            ull wj2 = pk(w[j], w[j]);
#pragma unroll
            for (int r = 0; r < 3; r++) {
                ulonglong2 q = Ab[j*3 + r];
                m01[r] = fma2(q.x, wj2, m01[r]);
                m23[r] = fma2(q.y, wj2, m23[r]);
            }
        }
        ull pxy = pk(px, py), pz1 = pk(pz, 1.0f);
        float* o = out + (size_t)b*Cn + 3*v;
#pragma unroll
        for (int r = 0; r < 3; r++) {
            ull t = fma2(m01[r], pxy, mul2(m23[r], pz1));
            float lo, hi; upk(t, lo, hi);
            o[r] = lo + hi;
        }
    }
}

// ---------------- K4: joints partials (SoA + packed f32x2) ------------------
__global__ void k_joints(const float* __restrict__ jr2, const float* __restrict__ out) {
    __shared__ float xs[16][66];
    __shared__ float ys[16][66];
    __shared__ float zs[16][66];
    __shared__ float jsh[43][66];
    const float* verts = out;
    int b0 = blockIdx.y * 16;
    int vs = blockIdx.x;
    int vstart = vs * 431;
    int vend = min(vstart + 431, Vn);

    ull ax2[3] = {0,0,0}, ay2[3] = {0,0,0}, az2[3] = {0,0,0};

    for (int vbase = vstart; vbase < vend; vbase += 64) {
        int vcnt = min(64, vend - vbase);
        for (int idx = threadIdx.x; idx < 16*64*3; idx += 256) {
            int bb = idx / 192; int rem = idx - bb*192;
            int vv = rem / 3;   int d = rem - vv*3;
            float val = (vv < vcnt) ? verts[(size_t)(b0 + bb)*Cn + (size_t)(vbase + vv)*3 + d] : 0.f;
            if (d == 0)      xs[bb][vv] = val;
            else if (d == 1) ys[bb][vv] = val;
            else             zs[bb][vv] = val;
        }
        for (int idx = threadIdx.x; idx < 43*64; idx += 256) {
            int j = idx >> 6; int vv = idx & 63;
            jsh[j][vv] = (vv < vcnt) ? jr2[(size_t)j*Vn + vbase + vv] : 0.f;
        }
        __syncthreads();
#pragma unroll
        for (int t = 0; t < 3; t++) {
            int pid = threadIdx.x + t*256;
            if (pid < 688) {
                int bb = pid / 43, j = pid - bb*43;
                const ull* jp = (const ull*)&jsh[j][0];
                const ull* xp = (const ull*)&xs[bb][0];
                const ull* yp = (const ull*)&ys[bb][0];
                const ull* zp = (const ull*)&zs[bb][0];
                ull sx = 0, sy = 0, sz = 0;
#pragma unroll 8
                for (int q = 0; q < 32; q++) {
                    ull jr = jp[q];
                    sx = fma2(jr, xp[q], sx);
                    sy = fma2(jr, yp[q], sy);
                    sz = fma2(jr, zp[q], sz);
                }
                ax2[t] = add2(ax2[t], sx);
                ay2[t] = add2(ay2[t], sy);
                az2[t] = add2(az2[t], sz);
            }
        }
        __syncthreads();
    }
#pragma unroll
    for (int t = 0; t < 3; t++) {
        int pid = threadIdx.x + t*256;
        if (pid < 688) {
            int bb = pid / 43, j = pid - bb*43;
            float* jo = &g_jpart[((size_t)vs*Bn*NJRn + (size_t)(b0 + bb)*NJRn + j)*3];
            float lo, hi;
            upk(ax2[t], lo, hi); jo[0] = lo + hi;
            upk(ay2[t], lo, hi); jo[1] = lo + hi;
            upk(az2[t], lo, hi); jo[2] = lo + hi;
        }
    }
}

// ---------------- K5: reduce joint partials ---------------------------------
__global__ void k_jred(float* __restrict__ out) {
    int i = blockIdx.x * blockDim.x + threadIdx.x;
    const int n = Bn*NJRn*3;
    if (i < n) {
        float s = 0.f;
#pragma unroll
        for (int vs = 0; vs < 16; vs++) s += g_jpart[(size_t)vs*n + i];
        out[(size_t)Bn*Cn + i] = s;
    }
}

// ---------------- launch -----------------------------------------------------
extern "C" void kernel_launch(void* const* d_in, const int* in_sizes, int n_in,
                              void* d_out, int out_size) {
    const float* beta  = (const float*)d_in[0];
    const float* theta = (const float*)d_in[1];
    const float* vt    = (const float*)d_in[2];
    const float* sd    = (const float*)d_in[3];
    const float* pd    = (const float*)d_in[4];
    const float* Jr    = (const float*)d_in[5];
    const float* jr2   = (const float*)d_in[6];
    const float* wts   = (const float*)d_in[7];
    float* out = (float*)d_out;

    k_pre<<<NJn, 256>>>(Jr, vt, sd);
    k_batch<<<Bn, 32>>>(beta, theta);
    k_vposed<<<dim3((Cn + 255)/256, Bn/32), 256>>>(vt, sd, pd);
    k_skin<<<dim3((Vn + 255)/256, Bn/8), 256>>>(wts, out);
    k_joints<<<dim3(16, 16), 256>>>(jr2, out);
    k_jred<<<(Bn*NJRn*3 + 255)/256, 256>>>(out);
}

// round 3
// speedup vs baseline: 1.3678x; 1.3186x over previous
#include <cuda_runtime.h>
#include <math.h>

#define Bn 256
#define Vn 6890
#define NJn 24
#define NBn 10
#define NPn 207
#define NJRn 43
#define Cn (Vn*3)       /* 20670 */
#define Cp 20672        /* padded vposed row stride (mult of 4) */
#define KC (NBn+NPn)    /* 217 */
#define KCP 224         /* padded K (28 chunks of 8) */
#define VSJ 48          /* v-splits for joints */
#define VSEG 144        /* vertices per split (48*144=6912>=6890) */

typedef unsigned long long ull;

__device__ __forceinline__ ull pk(float lo, float hi) {
    ull r; asm("mov.b64 %0,{%1,%2};" : "=l"(r) : "f"(lo), "f"(hi)); return r;
}
__device__ __forceinline__ void upk(ull v, float& lo, float& hi) {
    asm("mov.b64 {%0,%1},%2;" : "=f"(lo), "=f"(hi) : "l"(v));
}
__device__ __forceinline__ ull fma2(ull a, ull b, ull c) {
    ull d; asm("fma.rn.f32x2 %0,%1,%2,%3;" : "=l"(d) : "l"(a), "l"(b), "l"(c)); return d;
}
__device__ __forceinline__ ull mul2(ull a, ull b) {
    ull d; asm("mul.rn.f32x2 %0,%1,%2;" : "=l"(d) : "l"(a), "l"(b)); return d;
}

// ---------------- scratch ----------------------------------------------------
__device__ float g_coefT[KCP*Bn];            // [k][b], rows >=217 zero
__device__ float g_A[Bn*NJn*12];             // [b][24][3][4]
__device__ float g_prep[8*NJn*33];           // k_pre partials [s][j][33]
__device__ float g_JrSD[NJn*NBn*3];
__device__ float g_JrVT[NJn*3];
__device__ float g_vposed[(size_t)Bn*Cp + 128];
__device__ float g_jpart[(size_t)VSJ*Bn*44*3];

__constant__ int PARc[NJn] = {0,0,0,0,1,2,3,4,5,6,7,8,9,9,9,12,13,14,16,17,18,19,20,21};

// ---------------- K0a: Jr*vt and Jr*sd partial factors -----------------------
__global__ void k_pre(const float* __restrict__ Jr, const float* __restrict__ vt,
                      const float* __restrict__ sd) {
    int j = blockIdx.x;
    int s = blockIdx.y;
    int vstart = s * 862;
    int vend = min(vstart + 862, Vn);
    float acc[33];
#pragma unroll
    for (int e = 0; e < 33; e++) acc[e] = 0.f;

    for (int v = vstart + threadIdx.x; v < vend; v += 128) {
        float jr = Jr[j*Vn + v];
#pragma unroll
        for (int d = 0; d < 3; d++) acc[d] += jr * vt[v*3 + d];
#pragma unroll
        for (int k = 0; k < NBn; k++)
#pragma unroll
            for (int d = 0; d < 3; d++)
                acc[3 + k*3 + d] += jr * sd[(size_t)k*Cn + v*3 + d];
    }
#pragma unroll
    for (int off = 16; off; off >>= 1)
#pragma unroll
        for (int e = 0; e < 33; e++) acc[e] += __shfl_down_sync(0xffffffffu, acc[e], off);

    __shared__ float red[4][33];
    int w = threadIdx.x >> 5, l = threadIdx.x & 31;
    if (l == 0)
#pragma unroll
        for (int e = 0; e < 33; e++) red[w][e] = acc[e];
    __syncthreads();
    if (threadIdx.x < 33) {
        float t = red[0][threadIdx.x] + red[1][threadIdx.x] +
                  red[2][threadIdx.x] + red[3][threadIdx.x];
        g_prep[(s*NJn + j)*33 + threadIdx.x] = t;
    }
}

// ---------------- K0b: reduce partials ---------------------------------------
__global__ void k_pre2() {
    int i = blockIdx.x * blockDim.x + threadIdx.x;
    if (i < NJn*33) {
        int j = i / 33, e = i % 33;
        float s = 0.f;
#pragma unroll
        for (int ss = 0; ss < 8; ss++) s += g_prep[(ss*NJn + j)*33 + e];
        if (e < 3) g_JrVT[j*3 + e] = s;
        else       g_JrSD[j*30 + (e - 3)] = s;
    }
}

// ---------------- K1: rodrigues + chain + A + coefT ---------------------------
__global__ void k_batch(const float* __restrict__ beta, const float* __restrict__ theta) {
    int b = blockIdx.x;
    int lane = threadIdx.x;
    __shared__ float Rs[NJn*9];
    __shared__ float Jsh[NJn*3];
    __shared__ float G[NJn*12];

    if (lane < NJn) {
        int i = lane;
        float t0 = theta[b*72 + i*3 + 0];
        float t1 = theta[b*72 + i*3 + 1];
        float t2 = theta[b*72 + i*3 + 2];
        float a0 = t0 + 1e-8f, a1 = t1 + 1e-8f, a2 = t2 + 1e-8f;
        float angle = sqrtf(a0*a0 + a1*a1 + a2*a2);
        float inv = 1.0f / angle;
        float r0 = t0*inv, r1 = t1*inv, r2 = t2*inv;
        float s, c;
        sincosf(0.5f*angle, &s, &c);
        float qw = c, qx = s*r0, qy = s*r1, qz = s*r2;
        float qn = rsqrtf(qw*qw + qx*qx + qy*qy + qz*qz);
        qw *= qn; qx *= qn; qy *= qn; qz *= qn;
        float xx = qx*qx, yy = qy*qy, zz = qz*qz;
        float xy = qx*qy, xz = qx*qz, yz = qy*qz;
        float wx = qw*qx, wy = qw*qy, wz = qw*qz;
        Rs[i*9+0] = 1.f - 2.f*(yy+zz); Rs[i*9+1] = 2.f*(xy-wz);       Rs[i*9+2] = 2.f*(xz+wy);
        Rs[i*9+3] = 2.f*(xy+wz);       Rs[i*9+4] = 1.f - 2.f*(xx+zz); Rs[i*9+5] = 2.f*(yz-wx);
        Rs[i*9+6] = 2.f*(xz-wy);       Rs[i*9+7] = 2.f*(yz+wx);       Rs[i*9+8] = 1.f - 2.f*(xx+yy);
#pragma unroll
        for (int d = 0; d < 3; d++) {
            float sj = g_JrVT[i*3 + d];
#pragma unroll
            for (int k = 0; k < NBn; k++)
                sj += beta[b*NBn + k] * g_JrSD[i*30 + k*3 + d];
            Jsh[i*3 + d] = sj;
        }
    }
    __syncwarp();
    if (lane < 12) {
        int r = lane >> 2, c = lane & 3;
        float v;
        if (c < 3) v = Rs[r*3 + c] * (c == 0 ? 1.f : -1.f);
        else       v = Jsh[r];
        G[lane] = v;
    }
    __syncwarp();
    for (int i = 1; i < NJn; i++) {
        int p = PARc[i];
        float val = 0.f;
        if (lane < 12) {
            int r = lane >> 2, c = lane & 3;
#pragma unroll
            for (int m = 0; m < 3; m++) {
                float L = (c < 3) ? Rs[i*9 + m*3 + c] : (Jsh[i*3 + m] - Jsh[p*3 + m]);
                val += G[p*12 + r*4 + m] * L;
            }
            if (c == 3) val += G[p*12 + r*4 + 3];
        }
        __syncwarp();
        if (lane < 12) G[i*12 + lane] = val;
        __syncwarp();
    }
    if (lane < NJn) {
        int i = lane;
        float j0 = Jsh[i*3+0], j1 = Jsh[i*3+1], j2 = Jsh[i*3+2];
#pragma unroll
        for (int r = 0; r < 3; r++) {
            float g0 = G[i*12 + r*4 + 0], g1 = G[i*12 + r*4 + 1];
            float g2 = G[i*12 + r*4 + 2], g3 = G[i*12 + r*4 + 3];
            float* A = &g_A[((size_t)b*NJn + i)*12 + r*4];
            A[0] = g0; A[1] = g1; A[2] = g2;
            A[3] = g3 - (g0*j0 + g1*j1 + g2*j2);
        }
    }
    // coefT[k][b] = [beta(10), pose_feature(207)], rows 217..223 zero
    for (int idx = lane; idx < KCP; idx += 32) {
        float v = 0.f;
        if (idx < NBn) v = beta[b*NBn + idx];
        else if (idx < KC) {
            int e = idx - NBn;
            int i = e / 9 + 1;
            int rr = e % 9;
            v = Rs[i*9 + rr] - ((rr == 0 || rr == 4 || rr == 8) ? 1.f : 0.f);
        }
        g_coefT[idx*Bn + b] = v;
    }
}

// ---------------- K2: v_posed tiled GEMM (64c x 64b, 4x4/thread) -------------
__global__ void k_vposed(const float* __restrict__ vt, const float* __restrict__ sd,
                         const float* __restrict__ pd) {
    __shared__ float Ds[8][64];
    __shared__ float Cs[8][64];
    int cblk = blockIdx.x, bblk = blockIdx.y;
    int tid = threadIdx.x;
    int tx = tid & 15, ty = tid >> 4;        // tx: c-tile, ty: b-tile
    int gc0 = cblk*64 + tx*4;
    int gb0 = bblk*64 + ty*4;

    ull acc[4][2];
#pragma unroll
    for (int i = 0; i < 4; i++) { acc[i][0] = 0; acc[i][1] = 0; }

    int sk = tid >> 6;        // 0..3 (stage k pair of rows: handles k=sk and sk+4)
    int sc = tid & 63;

    for (int kk = 0; kk < 28; kk++) {
        int k0 = kk*8;
        // stage D (2 rows per thread), coef (2 rows per thread)
#pragma unroll
        for (int h = 0; h < 2; h++) {
            int k = sk + h*4;
            int gk = k0 + k;
            int gc = cblk*64 + sc;
            float dv = 0.f;
            if (gk < KC && gc < Cn)
                dv = (gk < NBn) ? sd[(size_t)gk*Cn + gc] : pd[(size_t)(gk - NBn)*Cn + gc];
            Ds[k][sc] = dv;
            Cs[k][sc] = g_coefT[(size_t)(k0 + k)*Bn + bblk*64 + sc];
        }
        __syncthreads();
#pragma unroll
        for (int k = 0; k < 8; k++) {
            ulonglong2 dq = *(const ulonglong2*)&Ds[k][tx*4];
            float4 cb = *(const float4*)&Cs[k][ty*4];
            ull c0 = pk(cb.x, cb.x), c1 = pk(cb.y, cb.y);
            ull c2 = pk(cb.z, cb.z), c3 = pk(cb.w, cb.w);
            acc[0][0] = fma2(dq.x, c0, acc[0][0]); acc[0][1] = fma2(dq.y, c0, acc[0][1]);
            acc[1][0] = fma2(dq.x, c1, acc[1][0]); acc[1][1] = fma2(dq.y, c1, acc[1][1]);
            acc[2][0] = fma2(dq.x, c2, acc[2][0]); acc[2][1] = fma2(dq.y, c2, acc[2][1]);
            acc[3][0] = fma2(dq.x, c3, acc[3][0]); acc[3][1] = fma2(dq.y, c3, acc[3][1]);
        }
        __syncthreads();
    }
    // epilogue: add v_template, write
    if (gc0 + 3 < Cn) {
        float4 v4 = *(const float4*)&vt[gc0];
#pragma unroll
        for (int i = 0; i < 4; i++) {
            float a0, a1, a2, a3;
            upk(acc[i][0], a0, a1);
            upk(acc[i][1], a2, a3);
            float4 o = make_float4(a0 + v4.x, a1 + v4.y, a2 + v4.z, a3 + v4.w);
            *(float4*)&g_vposed[(size_t)(gb0 + i)*Cp + gc0] = o;
        }
    } else {
#pragma unroll
        for (int i = 0; i < 4; i++) {
            float a[4];
            upk(acc[i][0], a[0], a[1]);
            upk(acc[i][1], a[2], a[3]);
#pragma unroll
            for (int e = 0; e < 4; e++) {
                int gc = gc0 + e;
                if (gc < Cn)
                    g_vposed[(size_t)(gb0 + i)*Cp + gc] = a[e] + vt[gc];
            }
        }
    }
}

// ---------------- K3: LBS skinning (4v x 1b per thread, warp=batch) ----------
__global__ void k_skin(const float* __restrict__ wts, float* __restrict__ out) {
    __shared__ float Wt[24][128];            // [j][v]
    __shared__ float A_sh[8*288];            // [b][j*12+r*4+c]
    int vblk = blockIdx.x, bblk = blockIdx.y;
    int tid = threadIdx.x;
    int lane = tid & 31, w = tid >> 5;       // w = local batch
    int bg = bblk*8 + w;

    // stage W (transpose) — weights broadcast across batch: slice 0 only
    for (int idx = tid; idx < 128*24; idx += 256) {
        int v = idx / 24, j = idx % 24;
        int gv = vblk*128 + v;
        Wt[j][v] = (gv < Vn) ? wts[(size_t)gv*24 + j] : 0.f;
    }
    for (int idx = tid; idx < 8*288; idx += 256)
        A_sh[idx] = g_A[(size_t)bblk*8*288 + idx];
    __syncthreads();

    int v0 = vblk*128 + lane*4;

    ull m01[4][3], m23[4][3];
#pragma unroll
    for (int i = 0; i < 4; i++)
#pragma unroll
        for (int r = 0; r < 3; r++) { m01[i][r] = 0; m23[i][r] = 0; }

    const float* Ab = &A_sh[w*288];
#pragma unroll 4
    for (int j = 0; j < 24; j++) {
        float4 w4 = *(const float4*)&Wt[j][lane*4];
        ulonglong2 q0 = *(const ulonglong2*)&Ab[j*12 + 0];   // row0: (c0,c1),(c2,c3)
        ulonglong2 q1 = *(const ulonglong2*)&Ab[j*12 + 4];
        ulonglong2 q2 = *(const ulonglong2*)&Ab[j*12 + 8];
        ull s0 = pk(w4.x, w4.x), s1 = pk(w4.y, w4.y);
        ull s2 = pk(w4.z, w4.z), s3 = pk(w4.w, w4.w);
        m01[0][0] = fma2(q0.x, s0, m01[0][0]); m23[0][0] = fma2(q0.y, s0, m23[0][0]);
        m01[0][1] = fma2(q1.x, s0, m01[0][1]); m23[0][1] = fma2(q1.y, s0, m23[0][1]);
        m01[0][2] = fma2(q2.x, s0, m01[0][2]); m23[0][2] = fma2(q2.y, s0, m23[0][2]);
        m01[1][0] = fma2(q0.x, s1, m01[1][0]); m23[1][0] = fma2(q0.y, s1, m23[1][0]);
        m01[1][1] = fma2(q1.x, s1, m01[1][1]); m23[1][1] = fma2(q1.y, s1, m23[1][1]);
        m01[1][2] = fma2(q2.x, s1, m01[1][2]); m23[1][2] = fma2(q2.y, s1, m23[1][2]);
        m01[2][0] = fma2(q0.x, s2, m01[2][0]); m23[2][0] = fma2(q0.y, s2, m23[2][0]);
        m01[2][1] = fma2(q1.x, s2, m01[2][1]); m23[2][1] = fma2(q1.y, s2, m23[2][1]);
        m01[2][2] = fma2(q2.x, s2, m01[2][2]); m23[2][2] = fma2(q2.y, s2, m23[2][2]);
        m01[3][0] = fma2(q0.x, s3, m01[3][0]); m23[3][0] = fma2(q0.y, s3, m23[3][0]);
        m01[3][1] = fma2(q1.x, s3, m01[3][1]); m23[3][1] = fma2(q1.y, s3, m23[3][1]);
        m01[3][2] = fma2(q2.x, s3, m01[3][2]); m23[3][2] = fma2(q2.y, s3, m23[3][2]);
    }

    // epilogue: apply to homogeneous v_posed, write verts
#pragma unroll
    for (int i = 0; i < 4; i++) {
        int v = v0 + i;
        if (v >= Vn) break;
        const float* vp = &g_vposed[(size_t)bg*Cp + 3*v];
        float px = vp[0], py = vp[1], pz = vp[2];
        ull pxy = pk(px, py), pz1 = pk(pz, 1.0f);
        float* o = out + (size_t)bg*Cn + 3*v;
#pragma unroll
        for (int r = 0; r < 3; r++) {
            ull t = fma2(m01[i][r], pxy, mul2(m23[i][r], pz1));
            float lo, hi; upk(t, lo, hi);
            o[r] = lo + hi;
        }
    }
}

// ---------------- K4: joints partials (4j x 4b per thread) -------------------
__global__ void k_joints(const float* __restrict__ jr2, const float* __restrict__ out) {
    __shared__ float xs[3][32][68];          // [d][v][b] padded
    __shared__ float jsh[32][48];            // [v][j] padded
    const float* verts = out;
    int vs = blockIdx.x, bblk = blockIdx.y;
    int b0 = bblk*64;
    int vstart = vs*VSEG;
    int vend = min(vstart + VSEG, Vn);
    int tid = threadIdx.x;

    bool active = tid < 176;
    int jt = tid % 11, bt = tid / 11;        // valid when active

    ull acc[4][3][2];
#pragma unroll
    for (int jj = 0; jj < 4; jj++)
#pragma unroll
        for (int d = 0; d < 3; d++) { acc[jj][d][0] = 0; acc[jj][d][1] = 0; }

    for (int vbase = vstart; vbase < vend; vbase += 32) {
        int vcnt = min(32, vend - vbase);
        // stage verts: read coalesced per batch, write SoA transposed
        for (int idx = tid; idx < 64*96; idx += 192) {
            int b = idx / 96, e = idx % 96;
            int v = e / 3, d = e % 3;
            float val = (v < vcnt) ? verts[(size_t)(b0 + b)*Cn + (size_t)(vbase + v)*3 + d] : 0.f;
            xs[d][v][b] = val;
        }
        // stage jr2: read coalesced over v, write [v][j]
        for (int idx = tid; idx < 44*32; idx += 192) {
            int j = idx >> 5, v = idx & 31;
            jsh[v][j] = (j < NJRn && v < vcnt) ? jr2[(size_t)j*Vn + vbase + v] : 0.f;
        }
        __syncthreads();
        if (active) {
#pragma unroll 4
            for (int v = 0; v < 32; v++) {
                float4 jr4 = *(const float4*)&jsh[v][jt*4];
                ull js0 = pk(jr4.x, jr4.x), js1 = pk(jr4.y, jr4.y);
                ull js2 = pk(jr4.z, jr4.z), js3 = pk(jr4.w, jr4.w);
#pragma unroll
                for (int d = 0; d < 3; d++) {
                    ulonglong2 xp = *(const ulonglong2*)&xs[d][v][bt*4];
                    acc[0][d][0] = fma2(xp.x, js0, acc[0][d][0]);
                    acc[0][d][1] = fma2(xp.y, js0, acc[0][d][1]);
                    acc[1][d][0] = fma2(xp.x, js1, acc[1][d][0]);
                    acc[1][d][1] = fma2(xp.y, js1, acc[1][d][1]);
                    acc[2][d][0] = fma2(xp.x, js2, acc[2][d][0]);
                    acc[2][d][1] = fma2(xp.y, js2, acc[2][d][1]);
                    acc[3][d][0] = fma2(xp.x, js3, acc[3][d][0]);
                    acc[3][d][1] = fma2(xp.y, js3, acc[3][d][1]);
                }
            }
        }
        __syncthreads();
    }
    if (active) {
#pragma unroll
        for (int jj = 0; jj < 4; jj++) {
            int j = jt*4 + jj;
#pragma unroll
            for (int d = 0; d < 3; d++) {
#pragma unroll
                for (int p = 0; p < 2; p++) {
                    float lo, hi;
                    upk(acc[jj][d][p], lo, hi);
                    int bA = b0 + bt*4 + 2*p;
                    g_jpart[((size_t)vs*Bn + bA)*132 + j*3 + d]     = lo;
                    g_jpart[((size_t)vs*Bn + bA + 1)*132 + j*3 + d] = hi;
                }
            }
        }
    }
}

// ---------------- K5: reduce joint partials ----------------------------------
__global__ void k_jred(float* __restrict__ out) {
    int i = blockIdx.x * blockDim.x + threadIdx.x;
    const int n = Bn*NJRn*3;   // 33024
    if (i < n) {
        int b = i / 129, r = i % 129;     // 129 = 43*3
        float s = 0.f;
#pragma unroll 8
        for (int vs = 0; vs < VSJ; vs++)
            s += g_jpart[((size_t)vs*Bn + b)*132 + r];
        out[(size_t)Bn*Cn + i] = s;
    }
}

// ---------------- launch ------------------------------------------------------
extern "C" void kernel_launch(void* const* d_in, const int* in_sizes, int n_in,
                              void* d_out, int out_size) {
    const float* beta  = (const float*)d_in[0];
    const float* theta = (const float*)d_in[1];
    const float* vt    = (const float*)d_in[2];
    const float* sd    = (const float*)d_in[3];
    const float* pd    = (const float*)d_in[4];
    const float* Jr    = (const float*)d_in[5];
    const float* jr2   = (const float*)d_in[6];
    const float* wts   = (const float*)d_in[7];
    float* out = (float*)d_out;

    k_pre<<<dim3(NJn, 8), 128>>>(Jr, vt, sd);
    k_pre2<<<(NJn*33 + 255)/256, 256>>>();
    k_batch<<<Bn, 32>>>(beta, theta);
    k_vposed<<<dim3(323, 4), 256>>>(vt, sd, pd);
    k_skin<<<dim3(54, 32), 256>>>(wts, out);
    k_joints<<<dim3(VSJ, 4), 192>>>(jr2, out);
    k_jred<<<(Bn*NJRn*3 + 255)/256, 256>>>(out);
}

// round 4
// speedup vs baseline: 1.4250x; 1.0418x over previous
#include <cuda_runtime.h>
#include <math.h>

#define Bn 256
#define Vn 6890
#define NJn 24
#define NBn 10
#define NPn 207
#define NJRn 43
#define Cn (Vn*3)       /* 20670 */
#define Cpad 20736      /* 81*256: padded columns */
#define KC2 218         /* 1 (vt) + 10 (beta) + 207 (pose) */
#define KCP 224         /* padded K: 28 chunks of 8 */
#define VSJ 48
#define VSEG 144

typedef unsigned long long ull;

__device__ __forceinline__ ull pk(float lo, float hi) {
    ull r; asm("mov.b64 %0,{%1,%2};" : "=l"(r) : "f"(lo), "f"(hi)); return r;
}
__device__ __forceinline__ void upk(ull v, float& lo, float& hi) {
    asm("mov.b64 {%0,%1},%2;" : "=f"(lo), "=f"(hi) : "l"(v));
}
__device__ __forceinline__ ull fma2(ull a, ull b, ull c) {
    ull d; asm("fma.rn.f32x2 %0,%1,%2,%3;" : "=l"(d) : "l"(a), "l"(b), "l"(c)); return d;
}
__device__ __forceinline__ ull mul2(ull a, ull b) {
    ull d; asm("mul.rn.f32x2 %0,%1,%2;" : "=l"(d) : "l"(a), "l"(b)); return d;
}

// ---------------- scratch ----------------------------------------------------
__device__ float g_Dall[(size_t)KCP*Cpad];   // [k][c]: row0=vt, 1..10=sd, 11..217=pd, rest 0
__device__ float g_coefT[KCP*Bn];            // [k][b]: row0=1, 1..10=beta, 11..217=pose, rest 0
__device__ float g_A[Bn*NJn*12];
__device__ float g_prep[8*NJn*33];
__device__ float g_JrSD[NJn*NBn*3];
__device__ float g_JrVT[NJn*3];
__device__ float g_vposed[(size_t)Bn*Cpad];
__device__ float g_jpart[(size_t)VSJ*Bn*44*3];

__constant__ int PARc[NJn] = {0,0,0,0,1,2,3,4,5,6,7,8,9,9,9,12,13,14,16,17,18,19,20,21};

// ---------------- K-1: build concatenated D matrix ---------------------------
__global__ void k_prepD(const float* __restrict__ vt, const float* __restrict__ sd,
                        const float* __restrict__ pd) {
    int i = blockIdx.x * blockDim.x + threadIdx.x;   // one float4 of output
    const int q = Cpad/4;                            // 5184
    if (i >= KCP*q) return;
    int row = i / q;
    int c0 = (i - row*q) * 4;
    float v[4];
#pragma unroll
    for (int e = 0; e < 4; e++) {
        int c = c0 + e;
        float x = 0.f;
        if (c < Cn && row < KC2) {
            if (row == 0)       x = vt[c];
            else if (row <= 10) x = sd[(size_t)(row-1)*Cn + c];
            else                x = pd[(size_t)(row-11)*Cn + c];
        }
        v[e] = x;
    }
    *(float4*)&g_Dall[(size_t)row*Cpad + c0] = make_float4(v[0], v[1], v[2], v[3]);
}

// ---------------- K0a: Jr*vt and Jr*sd partial factors -----------------------
__global__ void k_pre(const float* __restrict__ Jr, const float* __restrict__ vt,
                      const float* __restrict__ sd) {
    int j = blockIdx.x;
    int s = blockIdx.y;
    int vstart = s * 862;
    int vend = min(vstart + 862, Vn);
    float acc[33];
#pragma unroll
    for (int e = 0; e < 33; e++) acc[e] = 0.f;

    for (int v = vstart + threadIdx.x; v < vend; v += 128) {
        float jr = Jr[j*Vn + v];
#pragma unroll
        for (int d = 0; d < 3; d++) acc[d] += jr * vt[v*3 + d];
#pragma unroll
        for (int k = 0; k < NBn; k++)
#pragma unroll
            for (int d = 0; d < 3; d++)
                acc[3 + k*3 + d] += jr * sd[(size_t)k*Cn + v*3 + d];
    }
#pragma unroll
    for (int off = 16; off; off >>= 1)
#pragma unroll
        for (int e = 0; e < 33; e++) acc[e] += __shfl_down_sync(0xffffffffu, acc[e], off);

    __shared__ float red[4][33];
    int w = threadIdx.x >> 5, l = threadIdx.x & 31;
    if (l == 0)
#pragma unroll
        for (int e = 0; e < 33; e++) red[w][e] = acc[e];
    __syncthreads();
    if (threadIdx.x < 33) {
        float t = red[0][threadIdx.x] + red[1][threadIdx.x] +
                  red[2][threadIdx.x] + red[3][threadIdx.x];
        g_prep[(s*NJn + j)*33 + threadIdx.x] = t;
    }
}

// ---------------- K0b: reduce partials ---------------------------------------
__global__ void k_pre2() {
    int i = blockIdx.x * blockDim.x + threadIdx.x;
    if (i < NJn*33) {
        int j = i / 33, e = i % 33;
        float s = 0.f;
#pragma unroll
        for (int ss = 0; ss < 8; ss++) s += g_prep[(ss*NJn + j)*33 + e];
        if (e < 3) g_JrVT[j*3 + e] = s;
        else       g_JrSD[j*30 + (e - 3)] = s;
    }
}

// ---------------- K1: rodrigues + chain + A + coefT ---------------------------
__global__ void k_batch(const float* __restrict__ beta, const float* __restrict__ theta) {
    int b = blockIdx.x;
    int lane = threadIdx.x;
    __shared__ float Rs[NJn*9];
    __shared__ float Jsh[NJn*3];
    __shared__ float G[NJn*12];

    if (lane < NJn) {
        int i = lane;
        float t0 = theta[b*72 + i*3 + 0];
        float t1 = theta[b*72 + i*3 + 1];
        float t2 = theta[b*72 + i*3 + 2];
        float a0 = t0 + 1e-8f, a1 = t1 + 1e-8f, a2 = t2 + 1e-8f;
        float angle = sqrtf(a0*a0 + a1*a1 + a2*a2);
        float inv = 1.0f / angle;
        float r0 = t0*inv, r1 = t1*inv, r2 = t2*inv;
        float s, c;
        sincosf(0.5f*angle, &s, &c);
        float qw = c, qx = s*r0, qy = s*r1, qz = s*r2;
        float qn = rsqrtf(qw*qw + qx*qx + qy*qy + qz*qz);
        qw *= qn; qx *= qn; qy *= qn; qz *= qn;
        float xx = qx*qx, yy = qy*qy, zz = qz*qz;
        float xy = qx*qy, xz = qx*qz, yz = qy*qz;
        float wx = qw*qx, wy = qw*qy, wz = qw*qz;
        Rs[i*9+0] = 1.f - 2.f*(yy+zz); Rs[i*9+1] = 2.f*(xy-wz);       Rs[i*9+2] = 2.f*(xz+wy);
        Rs[i*9+3] = 2.f*(xy+wz);       Rs[i*9+4] = 1.f - 2.f*(xx+zz); Rs[i*9+5] = 2.f*(yz-wx);
        Rs[i*9+6] = 2.f*(xz-wy);       Rs[i*9+7] = 2.f*(yz+wx);       Rs[i*9+8] = 1.f - 2.f*(xx+yy);
#pragma unroll
        for (int d = 0; d < 3; d++) {
            float sj = g_JrVT[i*3 + d];
#pragma unroll
            for (int k = 0; k < NBn; k++)
                sj += beta[b*NBn + k] * g_JrSD[i*30 + k*3 + d];
            Jsh[i*3 + d] = sj;
        }
    }
    __syncwarp();
    if (lane < 12) {
        int r = lane >> 2, c = lane & 3;
        float v;
        if (c < 3) v = Rs[r*3 + c] * (c == 0 ? 1.f : -1.f);
        else       v = Jsh[r];
        G[lane] = v;
    }
    __syncwarp();
    for (int i = 1; i < NJn; i++) {
        int p = PARc[i];
        float val = 0.f;
        if (lane < 12) {
            int r = lane >> 2, c = lane & 3;
#pragma unroll
            for (int m = 0; m < 3; m++) {
                float L = (c < 3) ? Rs[i*9 + m*3 + c] : (Jsh[i*3 + m] - Jsh[p*3 + m]);
                val += G[p*12 + r*4 + m] * L;
            }
            if (c == 3) val += G[p*12 + r*4 + 3];
        }
        __syncwarp();
        if (lane < 12) G[i*12 + lane] = val;
        __syncwarp();
    }
    if (lane < NJn) {
        int i = lane;
        float j0 = Jsh[i*3+0], j1 = Jsh[i*3+1], j2 = Jsh[i*3+2];
#pragma unroll
        for (int r = 0; r < 3; r++) {
            float g0 = G[i*12 + r*4 + 0], g1 = G[i*12 + r*4 + 1];
            float g2 = G[i*12 + r*4 + 2], g3 = G[i*12 + r*4 + 3];
            float* A = &g_A[((size_t)b*NJn + i)*12 + r*4];
            A[0] = g0; A[1] = g1; A[2] = g2;
            A[3] = g3 - (g0*j0 + g1*j1 + g2*j2);
        }
    }
    // coefT[k][b]: row0 = 1 (vt), 1..10 beta, 11..217 pose, rest 0
    for (int idx = lane; idx < KCP; idx += 32) {
        float v = 0.f;
        if (idx == 0) v = 1.0f;
        else if (idx <= NBn) v = beta[b*NBn + idx - 1];
        else if (idx < KC2) {
            int e = idx - 11;
            int i = e / 9 + 1;
            int rr = e % 9;
            v = Rs[i*9 + rr] - ((rr == 0 || rr == 4 || rr == 8) ? 1.f : 0.f);
        }
        g_coefT[idx*Bn + b] = v;
    }
}

// ---------------- K2: v_posed GEMM (256c x 64b block, 8x8/thread) ------------
__global__ void __launch_bounds__(256, 2) k_vposed() {
    __shared__ float Ds[2][8][256];
    __shared__ float Cs[2][8][128];   // dup'd pairs: [k][2*bb] = (c,c)
    int cblk = blockIdx.x, bblk = blockIdx.y;
    int t = threadIdx.x, l = t & 31, w = t >> 5;
    int tk = t >> 6, tc = t & 63;     // staging coords

    ull acc[8][4];
#pragma unroll
    for (int bb = 0; bb < 8; bb++)
#pragma unroll
        for (int cp = 0; cp < 4; cp++) acc[bb][cp] = 0;

    size_t dbase = (size_t)cblk*256 + (size_t)tc*4;
    const float* cbase = g_coefT + bblk*64 + tc;

    float4 rd0, rd1; float rc0, rc1;
    // prefetch chunk 0
    {
        rd0 = *(const float4*)&g_Dall[(size_t)tk*Cpad + dbase];
        rd1 = *(const float4*)&g_Dall[(size_t)(tk+4)*Cpad + dbase];
        rc0 = cbase[(size_t)tk*Bn];
        rc1 = cbase[(size_t)(tk+4)*Bn];
    }
    *(float4*)&Ds[0][tk][tc*4]   = rd0;
    *(float4*)&Ds[0][tk+4][tc*4] = rd1;
    *(ull*)&Cs[0][tk][tc*2]   = pk(rc0, rc0);
    *(ull*)&Cs[0][tk+4][tc*2] = pk(rc1, rc1);
    __syncthreads();

    int buf = 0;
    for (int kk = 0; kk < 28; kk++) {
        if (kk + 1 < 28) {
            int k0 = (kk+1)*8;
            rd0 = *(const float4*)&g_Dall[(size_t)(k0+tk)*Cpad + dbase];
            rd1 = *(const float4*)&g_Dall[(size_t)(k0+tk+4)*Cpad + dbase];
            rc0 = cbase[(size_t)(k0+tk)*Bn];
            rc1 = cbase[(size_t)(k0+tk+4)*Bn];
        }
#pragma unroll
        for (int k = 0; k < 8; k++) {
            ulonglong2 dA = *(const ulonglong2*)&Ds[buf][k][l*4];
            ulonglong2 dB = *(const ulonglong2*)&Ds[buf][k][128 + l*4];
            const ulonglong2* cw = (const ulonglong2*)&Cs[buf][k][w*16];
            ulonglong2 c01 = cw[0], c23 = cw[1], c45 = cw[2], c67 = cw[3];
            acc[0][0] = fma2(dA.x, c01.x, acc[0][0]); acc[0][1] = fma2(dA.y, c01.x, acc[0][1]);
            acc[0][2] = fma2(dB.x, c01.x, acc[0][2]); acc[0][3] = fma2(dB.y, c01.x, acc[0][3]);
            acc[1][0] = fma2(dA.x, c01.y, acc[1][0]); acc[1][1] = fma2(dA.y, c01.y, acc[1][1]);
            acc[1][2] = fma2(dB.x, c01.y, acc[1][2]); acc[1][3] = fma2(dB.y, c01.y, acc[1][3]);
            acc[2][0] = fma2(dA.x, c23.x, acc[2][0]); acc[2][1] = fma2(dA.y, c23.x, acc[2][1]);
            acc[2][2] = fma2(dB.x, c23.x, acc[2][2]); acc[2][3] = fma2(dB.y, c23.x, acc[2][3]);
            acc[3][0] = fma2(dA.x, c23.y, acc[3][0]); acc[3][1] = fma2(dA.y, c23.y, acc[3][1]);
            acc[3][2] = fma2(dB.x, c23.y, acc[3][2]); acc[3][3] = fma2(dB.y, c23.y, acc[3][3]);
            acc[4][0] = fma2(dA.x, c45.x, acc[4][0]); acc[4][1] = fma2(dA.y, c45.x, acc[4][1]);
            acc[4][2] = fma2(dB.x, c45.x, acc[4][2]); acc[4][3] = fma2(dB.y, c45.x, acc[4][3]);
            acc[5][0] = fma2(dA.x, c45.y, acc[5][0]); acc[5][1] = fma2(dA.y, c45.y, acc[5][1]);
            acc[5][2] = fma2(dB.x, c45.y, acc[5][2]); acc[5][3] = fma2(dB.y, c45.y, acc[5][3]);
            acc[6][0] = fma2(dA.x, c67.x, acc[6][0]); acc[6][1] = fma2(dA.y, c67.x, acc[6][1]);
            acc[6][2] = fma2(dB.x, c67.x, acc[6][2]); acc[6][3] = fma2(dB.y, c67.x, acc[6][3]);
            acc[7][0] = fma2(dA.x, c67.y, acc[7][0]); acc[7][1] = fma2(dA.y, c67.y, acc[7][1]);
            acc[7][2] = fma2(dB.x, c67.y, acc[7][2]); acc[7][3] = fma2(dB.y, c67.y, acc[7][3]);
        }
        if (kk + 1 < 28) {
            int nb = buf ^ 1;
            *(float4*)&Ds[nb][tk][tc*4]   = rd0;
            *(float4*)&Ds[nb][tk+4][tc*4] = rd1;
            *(ull*)&Cs[nb][tk][tc*2]   = pk(rc0, rc0);
            *(ull*)&Cs[nb][tk+4][tc*2] = pk(rc1, rc1);
            buf = nb;
            __syncthreads();
        }
    }
    // epilogue: vt already folded in (k=0 row). Write 8 batches x 8 cols.
#pragma unroll
    for (int bb = 0; bb < 8; bb++) {
        int b = bblk*64 + w*8 + bb;
        float* row = g_vposed + (size_t)b*Cpad + cblk*256;
        ulonglong2 lo; lo.x = acc[bb][0]; lo.y = acc[bb][1];
        ulonglong2 hi; hi.x = acc[bb][2]; hi.y = acc[bb][3];
        *(ulonglong2*)&row[l*4]       = lo;
        *(ulonglong2*)&row[128 + l*4] = hi;
    }
}

// ---------------- K3: LBS skinning (4v x 1b per thread, warp=batch) ----------
__global__ void k_skin(const float* __restrict__ wts, float* __restrict__ out) {
    __shared__ float Wt[24][128];
    __shared__ float A_sh[8*288];
    int vblk = blockIdx.x, bblk = blockIdx.y;
    int tid = threadIdx.x;
    int lane = tid & 31, w = tid >> 5;
    int bg = bblk*8 + w;

    for (int idx = tid; idx < 128*24; idx += 256) {
        int v = idx / 24, j = idx % 24;
        int gv = vblk*128 + v;
        Wt[j][v] = (gv < Vn) ? wts[(size_t)gv*24 + j] : 0.f;
    }
    for (int idx = tid; idx < 8*288; idx += 256)
        A_sh[idx] = g_A[(size_t)bblk*8*288 + idx];
    __syncthreads();

    int v0 = vblk*128 + lane*4;

    ull m01[4][3], m23[4][3];
#pragma unroll
    for (int i = 0; i < 4; i++)
#pragma unroll
        for (int r = 0; r < 3; r++) { m01[i][r] = 0; m23[i][r] = 0; }

    const float* Ab = &A_sh[w*288];
#pragma unroll 4
    for (int j = 0; j < 24; j++) {
        float4 w4 = *(const float4*)&Wt[j][lane*4];
        ulonglong2 q0 = *(const ulonglong2*)&Ab[j*12 + 0];
        ulonglong2 q1 = *(const ulonglong2*)&Ab[j*12 + 4];
        ulonglong2 q2 = *(const ulonglong2*)&Ab[j*12 + 8];
        ull s0 = pk(w4.x, w4.x), s1 = pk(w4.y, w4.y);
        ull s2 = pk(w4.z, w4.z), s3 = pk(w4.w, w4.w);
        m01[0][0] = fma2(q0.x, s0, m01[0][0]); m23[0][0] = fma2(q0.y, s0, m23[0][0]);
        m01[0][1] = fma2(q1.x, s0, m01[0][1]); m23[0][1] = fma2(q1.y, s0, m23[0][1]);
        m01[0][2] = fma2(q2.x, s0, m01[0][2]); m23[0][2] = fma2(q2.y, s0, m23[0][2]);
        m01[1][0] = fma2(q0.x, s1, m01[1][0]); m23[1][0] = fma2(q0.y, s1, m23[1][0]);
        m01[1][1] = fma2(q1.x, s1, m01[1][1]); m23[1][1] = fma2(q1.y, s1, m23[1][1]);
        m01[1][2] = fma2(q2.x, s1, m01[1][2]); m23[1][2] = fma2(q2.y, s1, m23[1][2]);
        m01[2][0] = fma2(q0.x, s2, m01[2][0]); m23[2][0] = fma2(q0.y, s2, m23[2][0]);
        m01[2][1] = fma2(q1.x, s2, m01[2][1]); m23[2][1] = fma2(q1.y, s2, m23[2][1]);
        m01[2][2] = fma2(q2.x, s2, m01[2][2]); m23[2][2] = fma2(q2.y, s2, m23[2][2]);
        m01[3][0] = fma2(q0.x, s3, m01[3][0]); m23[3][0] = fma2(q0.y, s3, m23[3][0]);
        m01[3][1] = fma2(q1.x, s3, m01[3][1]); m23[3][1] = fma2(q1.y, s3, m23[3][1]);
        m01[3][2] = fma2(q2.x, s3, m01[3][2]); m23[3][2] = fma2(q2.y, s3, m23[3][2]);
    }

#pragma unroll
    for (int i = 0; i < 4; i++) {
        int v = v0 + i;
        if (v >= Vn) break;
        const float* vp = &g_vposed[(size_t)bg*Cpad + 3*v];
        float px = vp[0], py = vp[1], pz = vp[2];
        ull pxy = pk(px, py), pz1 = pk(pz, 1.0f);
        float* o = out + (size_t)bg*Cn + 3*v;
#pragma unroll
        for (int r = 0; r < 3; r++) {
            ull t = fma2(m01[i][r], pxy, mul2(m23[i][r], pz1));
            float lo, hi; upk(t, lo, hi);
            o[r] = lo + hi;
        }
    }
}

// ---------------- K4: joints partials (4j x 4b per thread) -------------------
__global__ void k_joints(const float* __restrict__ jr2, const float* __restrict__ out) {
    __shared__ float xs[3][32][68];
    __shared__ float jsh[32][48];
    const float* verts = out;
    int vs = blockIdx.x, bblk = blockIdx.y;
    int b0 = bblk*64;
    int vstart = vs*VSEG;
    int vend = min(vstart + VSEG, Vn);
    int tid = threadIdx.x;

    bool active = tid < 176;
    int jt = tid % 11, bt = tid / 11;

    ull acc[4][3][2];
#pragma unroll
    for (int jj = 0; jj < 4; jj++)
#pragma unroll
        for (int d = 0; d < 3; d++) { acc[jj][d][0] = 0; acc[jj][d][1] = 0; }

    for (int vbase = vstart; vbase < vend; vbase += 32) {
        int vcnt = min(32, vend - vbase);
        for (int idx = tid; idx < 64*96; idx += 192) {
            int b = idx / 96, e = idx % 96;
            int v = e / 3, d = e % 3;
            float val = (v < vcnt) ? verts[(size_t)(b0 + b)*Cn + (size_t)(vbase + v)*3 + d] : 0.f;
            xs[d][v][b] = val;
        }
        for (int idx = tid; idx < 44*32; idx += 192) {
            int j = idx >> 5, v = idx & 31;
            jsh[v][j] = (j < NJRn && v < vcnt) ? jr2[(size_t)j*Vn + vbase + v] : 0.f;
        }
        __syncthreads();
        if (active) {
#pragma unroll 4
            for (int v = 0; v < 32; v++) {
                float4 jr4 = *(const float4*)&jsh[v][jt*4];
                ull js0 = pk(jr4.x, jr4.x), js1 = pk(jr4.y, jr4.y);
                ull js2 = pk(jr4.z, jr4.z), js3 = pk(jr4.w, jr4.w);
#pragma unroll
                for (int d = 0; d < 3; d++) {
                    ulonglong2 xp = *(const ulonglong2*)&xs[d][v][bt*4];
                    acc[0][d][0] = fma2(xp.x, js0, acc[0][d][0]);
                    acc[0][d][1] = fma2(xp.y, js0, acc[0][d][1]);
                    acc[1][d][0] = fma2(xp.x, js1, acc[1][d][0]);
                    acc[1][d][1] = fma2(xp.y, js1, acc[1][d][1]);
                    acc[2][d][0] = fma2(xp.x, js2, acc[2][d][0]);
                    acc[2][d][1] = fma2(xp.y, js2, acc[2][d][1]);
                    acc[3][d][0] = fma2(xp.x, js3, acc[3][d][0]);
                    acc[3][d][1] = fma2(xp.y, js3, acc[3][d][1]);
                }
            }
        }
        __syncthreads();
    }
    if (active) {
#pragma unroll
        for (int jj = 0; jj < 4; jj++) {
            int j = jt*4 + jj;
#pragma unroll
            for (int d = 0; d < 3; d++) {
#pragma unroll
                for (int p = 0; p < 2; p++) {
                    float lo, hi;
                    upk(acc[jj][d][p], lo, hi);
                    int bA = b0 + bt*4 + 2*p;
                    g_jpart[((size_t)vs*Bn + bA)*132 + j*3 + d]     = lo;
                    g_jpart[((size_t)vs*Bn + bA + 1)*132 + j*3 + d] = hi;
                }
            }
        }
    }
}

// ---------------- K5: reduce joint partials ----------------------------------
__global__ void k_jred(float* __restrict__ out) {
    int i = blockIdx.x * blockDim.x + threadIdx.x;
    const int n = Bn*NJRn*3;
    if (i < n) {
        int b = i / 129, r = i % 129;
        float s = 0.f;
#pragma unroll 8
        for (int vs = 0; vs < VSJ; vs++)
            s += g_jpart[((size_t)vs*Bn + b)*132 + r];
        out[(size_t)Bn*Cn + i] = s;
    }
}

// ---------------- launch ------------------------------------------------------
extern "C" void kernel_launch(void* const* d_in, const int* in_sizes, int n_in,
                              void* d_out, int out_size) {
    const float* beta  = (const float*)d_in[0];
    const float* theta = (const float*)d_in[1];
    const float* vt    = (const float*)d_in[2];
    const float* sd    = (const float*)d_in[3];
    const float* pd    = (const float*)d_in[4];
    const float* Jr    = (const float*)d_in[5];
    const float* jr2   = (const float*)d_in[6];
    const float* wts   = (const float*)d_in[7];
    float* out = (float*)d_out;

    k_prepD<<<(KCP*(Cpad/4) + 255)/256, 256>>>(vt, sd, pd);
    k_pre<<<dim3(NJn, 8), 128>>>(Jr, vt, sd);
    k_pre2<<<(NJn*33 + 255)/256, 256>>>();
    k_batch<<<Bn, 32>>>(beta, theta);
    k_vposed<<<dim3(Cpad/256, Bn/64), 256>>>();
    k_skin<<<dim3(54, 32), 256>>>(wts, out);
    k_joints<<<dim3(VSJ, 4), 192>>>(jr2, out);
    k_jred<<<(Bn*NJRn*3 + 255)/256, 256>>>(out);
}